// round 2
// baseline (speedup 1.0000x reference)
#include <cuda_runtime.h>
#include <math.h>

#define HID    1024
#define NHEADS 16
#define HDIM   64
#define NB     2
#define SEQ    2048
#define NBH    (NB*NHEADS)
#define KKEEP  1024

// ---------------- scratch (allocation-free: __device__ globals) ----------------
__device__ float g_q[(size_t)NBH * SEQ * HDIM];     // [B,H,S,D]  16 MB
__device__ float g_k[(size_t)NBH * SEQ * HDIM];     // 16 MB
__device__ float g_v[(size_t)NBH * SEQ * HDIM];     // 16 MB
__device__ float g_p[(size_t)NBH * SEQ * SEQ];      // [B,H,S,S]  536 MB (scores -> probs in-place)
__device__ float g_ctx[(size_t)NB * SEQ * HID];     // [B,S,H*D]  16 MB

// ---------------- block reduces ----------------
__device__ __forceinline__ float warp_max_f(float v) {
#pragma unroll
    for (int o = 16; o > 0; o >>= 1) v = fmaxf(v, __shfl_xor_sync(0xffffffffu, v, o));
    return v;
}
__device__ __forceinline__ float warp_sum_f(float v) {
#pragma unroll
    for (int o = 16; o > 0; o >>= 1) v += __shfl_xor_sync(0xffffffffu, v, o);
    return v;
}
__device__ __forceinline__ int warp_sum_i(int v) {
#pragma unroll
    for (int o = 16; o > 0; o >>= 1) v += __shfl_xor_sync(0xffffffffu, v, o);
    return v;
}
__device__ __forceinline__ float block_max_f(float v, float* sm) {
    v = warp_max_f(v);
    if ((threadIdx.x & 31) == 0) sm[threadIdx.x >> 5] = v;
    __syncthreads();
    if (threadIdx.x == 0) {
        float r = sm[0];
#pragma unroll
        for (int i = 1; i < 8; i++) r = fmaxf(r, sm[i]);
        sm[0] = r;
    }
    __syncthreads();
    v = sm[0];
    __syncthreads();
    return v;
}
__device__ __forceinline__ float block_sum_f(float v, float* sm) {
    v = warp_sum_f(v);
    if ((threadIdx.x & 31) == 0) sm[threadIdx.x >> 5] = v;
    __syncthreads();
    if (threadIdx.x == 0) {
        float r = sm[0];
#pragma unroll
        for (int i = 1; i < 8; i++) r += sm[i];
        sm[0] = r;
    }
    __syncthreads();
    v = sm[0];
    __syncthreads();
    return v;
}
__device__ __forceinline__ int block_sum_i(int v, int* sm) {
    v = warp_sum_i(v);
    if ((threadIdx.x & 31) == 0) sm[threadIdx.x >> 5] = v;
    __syncthreads();
    if (threadIdx.x == 0) {
        int r = sm[0];
#pragma unroll
        for (int i = 1; i < 8; i++) r += sm[i];
        sm[0] = r;
    }
    __syncthreads();
    v = sm[0];
    __syncthreads();
    return v;
}

// ---------------- GEMM 1: QKV projection, C = X @ W^T scattered to [B,H,S,D] ----------------
// 64x64 block tile, BK=16, 256 threads, 4x4 per thread.
__global__ void proj_kernel(const float* __restrict__ x,
                            const float* __restrict__ Wq,
                            const float* __restrict__ Wk,
                            const float* __restrict__ Wv) {
    const float* W;
    float* outp;
    if (blockIdx.z == 0)      { W = Wq; outp = g_q; }
    else if (blockIdx.z == 1) { W = Wk; outp = g_k; }
    else                      { W = Wv; outp = g_v; }

    __shared__ float As[16][64];   // [k][m]
    __shared__ float Bs[16][64];   // [k][n]

    const int K = HID;
    int m0 = blockIdx.y * 64;
    int n0 = blockIdx.x * 64;
    int tid = threadIdx.x;
    int tx = tid & 15, ty = tid >> 4;
    int lr = tid >> 2, lc = (tid & 3) << 2;

    float acc[4][4] = {};

    for (int k0 = 0; k0 < K; k0 += 16) {
        float4 a4 = *(const float4*)(x + (size_t)(m0 + lr) * K + k0 + lc);
        float4 b4 = *(const float4*)(W + (size_t)(n0 + lr) * K + k0 + lc);
        As[lc+0][lr] = a4.x; As[lc+1][lr] = a4.y; As[lc+2][lr] = a4.z; As[lc+3][lr] = a4.w;
        Bs[lc+0][lr] = b4.x; Bs[lc+1][lr] = b4.y; Bs[lc+2][lr] = b4.z; Bs[lc+3][lr] = b4.w;
        __syncthreads();
#pragma unroll
        for (int kk = 0; kk < 16; kk++) {
            float4 a = *(const float4*)&As[kk][ty << 2];
            float4 b = *(const float4*)&Bs[kk][tx << 2];
            float ar[4] = {a.x, a.y, a.z, a.w};
            float br[4] = {b.x, b.y, b.z, b.w};
#pragma unroll
            for (int i = 0; i < 4; i++)
#pragma unroll
                for (int j = 0; j < 4; j++)
                    acc[i][j] += ar[i] * br[j];
        }
        __syncthreads();
    }

    int n = n0 + (tx << 2);
    int h = n >> 6, d = n & 63;
#pragma unroll
    for (int i = 0; i < 4; i++) {
        int m = m0 + (ty << 2) + i;
        int b = m / SEQ, s = m % SEQ;
        float4 o = make_float4(acc[i][0], acc[i][1], acc[i][2], acc[i][3]);
        *(float4*)(outp + (((size_t)(b * NHEADS + h) * SEQ + s) * HDIM + d)) = o;
    }
}

// ---------------- GEMM 2: scores = Q K^T * 1/8 per (b,h) ----------------
__global__ void scores_kernel() {
    int bh = blockIdx.z;
    const float* A  = g_q + (size_t)bh * SEQ * HDIM;
    const float* Bm = g_k + (size_t)bh * SEQ * HDIM;
    float* C = g_p + (size_t)bh * SEQ * SEQ;

    __shared__ float As[16][64];
    __shared__ float Bs[16][64];

    int m0 = blockIdx.y * 64;
    int n0 = blockIdx.x * 64;
    int tid = threadIdx.x;
    int tx = tid & 15, ty = tid >> 4;
    int lr = tid >> 2, lc = (tid & 3) << 2;

    float acc[4][4] = {};

    for (int k0 = 0; k0 < HDIM; k0 += 16) {
        float4 a4 = *(const float4*)(A  + (size_t)(m0 + lr) * HDIM + k0 + lc);
        float4 b4 = *(const float4*)(Bm + (size_t)(n0 + lr) * HDIM + k0 + lc);
        As[lc+0][lr] = a4.x; As[lc+1][lr] = a4.y; As[lc+2][lr] = a4.z; As[lc+3][lr] = a4.w;
        Bs[lc+0][lr] = b4.x; Bs[lc+1][lr] = b4.y; Bs[lc+2][lr] = b4.z; Bs[lc+3][lr] = b4.w;
        __syncthreads();
#pragma unroll
        for (int kk = 0; kk < 16; kk++) {
            float4 a = *(const float4*)&As[kk][ty << 2];
            float4 b = *(const float4*)&Bs[kk][tx << 2];
            float ar[4] = {a.x, a.y, a.z, a.w};
            float br[4] = {b.x, b.y, b.z, b.w};
#pragma unroll
            for (int i = 0; i < 4; i++)
#pragma unroll
                for (int j = 0; j < 4; j++)
                    acc[i][j] += ar[i] * br[j];
        }
        __syncthreads();
    }

#pragma unroll
    for (int i = 0; i < 4; i++) {
        int m = m0 + (ty << 2) + i;
        float4 o = make_float4(acc[i][0]*0.125f, acc[i][1]*0.125f,
                               acc[i][2]*0.125f, acc[i][3]*0.125f);
        *(float4*)(C + (size_t)m * SEQ + n0 + (tx << 2)) = o;
    }
}

// ---------------- kernel 3: exact top-k(1024) threshold + masked softmax, in-place ----------------
// One block per score row. Row lives in registers (8 vals/thread). k-th largest found
// by 32-step binary search over order-preserving uint keys (exact tie semantics).
__global__ void topk_softmax_kernel(const float* __restrict__ thr_ptr) {
    __shared__ float smf[8];
    __shared__ int   smi[8];

    size_t row = blockIdx.x;
    float* p = g_p + row * SEQ;
    int tid = threadIdx.x;

    float v[8];
    unsigned key[8];
#pragma unroll
    for (int i = 0; i < 8; i++) {
        v[i] = p[tid + (i << 8)];
        unsigned bb = __float_as_uint(v[i]);
        key[i] = (bb & 0x80000000u) ? ~bb : (bb | 0x80000000u);
    }

    float lm = v[0];
#pragma unroll
    for (int i = 1; i < 8; i++) lm = fmaxf(lm, v[i]);
    float m = block_max_f(lm, smf);

    // binary search: largest key T with count(key >= T) >= KKEEP  == key of k-th largest
    unsigned lo = 0u, hi = 0xFFFFFFFFu;
    while (lo < hi) {
        unsigned mid = lo + ((hi - lo) >> 1) + 1u;
        int c = 0;
#pragma unroll
        for (int i = 0; i < 8; i++) c += (key[i] >= mid) ? 1 : 0;
        c = block_sum_i(c, smi);
        if (c >= KKEEP) lo = mid; else hi = mid - 1u;
    }
    float t = __uint_as_float((lo & 0x80000000u) ? (lo ^ 0x80000000u) : ~lo);

    float thr = thr_ptr[0];
    thr = fminf(fmaxf(thr, 0.0f), 1.0f);
    float teff = fmaxf(t, thr);   // keep iff v >= kth AND v >= thr

    float e[8];
    float ls = 0.0f;
#pragma unroll
    for (int i = 0; i < 8; i++) {
        e[i] = (v[i] >= teff) ? expf(v[i] - m) : 0.0f;
        ls += e[i];
    }
    float s = block_sum_f(ls, smf);
    float inv = 1.0f / s;
#pragma unroll
    for (int i = 0; i < 8; i++) p[tid + (i << 8)] = e[i] * inv;
}

// ---------------- GEMM 3: ctx = P @ V per (b,h), gathered to [B,S,H*D] ----------------
__global__ void av_kernel() {
    int bh = blockIdx.z;
    int b = bh >> 4, h = bh & 15;
    const float* A  = g_p + (size_t)bh * SEQ * SEQ;    // [S,S] row-major
    const float* Bv = g_v + (size_t)bh * SEQ * HDIM;   // [S,64] row-major (NN gemm)

    __shared__ float As[16][64];   // [k][m]
    __shared__ float Bs[16][64];   // [k][n]

    int m0 = blockIdx.y * 64;
    int tid = threadIdx.x;
    int tx = tid & 15, ty = tid >> 4;
    int lr = tid >> 2, lc = (tid & 3) << 2;     // A loader
    int brw = tid >> 4, bcl = (tid & 15) << 2;  // B loader: 16 rows x 64 cols

    float acc[4][4] = {};

    for (int k0 = 0; k0 < SEQ; k0 += 16) {
        float4 a4 = *(const float4*)(A + (size_t)(m0 + lr) * SEQ + k0 + lc);
        As[lc+0][lr] = a4.x; As[lc+1][lr] = a4.y; As[lc+2][lr] = a4.z; As[lc+3][lr] = a4.w;
        float4 b4 = *(const float4*)(Bv + (size_t)(k0 + brw) * HDIM + bcl);
        *(float4*)&Bs[brw][bcl] = b4;
        __syncthreads();
#pragma unroll
        for (int kk = 0; kk < 16; kk++) {
            float4 a = *(const float4*)&As[kk][ty << 2];
            float4 b = *(const float4*)&Bs[kk][tx << 2];
            float ar[4] = {a.x, a.y, a.z, a.w};
            float br[4] = {b.x, b.y, b.z, b.w};
#pragma unroll
            for (int i = 0; i < 4; i++)
#pragma unroll
                for (int j = 0; j < 4; j++)
                    acc[i][j] += ar[i] * br[j];
        }
        __syncthreads();
    }

#pragma unroll
    for (int i = 0; i < 4; i++) {
        int m = m0 + (ty << 2) + i;   // query position s
        float4 o = make_float4(acc[i][0], acc[i][1], acc[i][2], acc[i][3]);
        *(float4*)(g_ctx + ((size_t)(b * SEQ + m) * HID + h * HDIM + (tx << 2))) = o;
    }
}

// ---------------- GEMM 4: out = ctx @ Wo^T + bo ----------------
__global__ void final_kernel(const float* __restrict__ Wo,
                             const float* __restrict__ bo,
                             float* __restrict__ out) {
    __shared__ float As[16][64];
    __shared__ float Bs[16][64];

    const int K = HID;
    int m0 = blockIdx.y * 64;
    int n0 = blockIdx.x * 64;
    int tid = threadIdx.x;
    int tx = tid & 15, ty = tid >> 4;
    int lr = tid >> 2, lc = (tid & 3) << 2;

    float acc[4][4] = {};

    for (int k0 = 0; k0 < K; k0 += 16) {
        float4 a4 = *(const float4*)(g_ctx + (size_t)(m0 + lr) * K + k0 + lc);
        float4 b4 = *(const float4*)(Wo    + (size_t)(n0 + lr) * K + k0 + lc);
        As[lc+0][lr] = a4.x; As[lc+1][lr] = a4.y; As[lc+2][lr] = a4.z; As[lc+3][lr] = a4.w;
        Bs[lc+0][lr] = b4.x; Bs[lc+1][lr] = b4.y; Bs[lc+2][lr] = b4.z; Bs[lc+3][lr] = b4.w;
        __syncthreads();
#pragma unroll
        for (int kk = 0; kk < 16; kk++) {
            float4 a = *(const float4*)&As[kk][ty << 2];
            float4 b = *(const float4*)&Bs[kk][tx << 2];
            float ar[4] = {a.x, a.y, a.z, a.w};
            float br[4] = {b.x, b.y, b.z, b.w};
#pragma unroll
            for (int i = 0; i < 4; i++)
#pragma unroll
                for (int j = 0; j < 4; j++)
                    acc[i][j] += ar[i] * br[j];
        }
        __syncthreads();
    }

    int n = n0 + (tx << 2);
    float4 bias = *(const float4*)(bo + n);
#pragma unroll
    for (int i = 0; i < 4; i++) {
        int m = m0 + (ty << 2) + i;
        float4 o = make_float4(acc[i][0] + bias.x, acc[i][1] + bias.y,
                               acc[i][2] + bias.z, acc[i][3] + bias.w);
        *(float4*)(out + (size_t)m * HID + n) = o;
    }
}

// ---------------- launch ----------------
extern "C" void kernel_launch(void* const* d_in, const int* in_sizes, int n_in,
                              void* d_out, int out_size) {
    const float* x   = (const float*)d_in[0];
    const float* Wq  = (const float*)d_in[1];
    const float* Wk  = (const float*)d_in[2];
    const float* Wv  = (const float*)d_in[3];
    const float* Wo  = (const float*)d_in[4];
    const float* bo  = (const float*)d_in[5];
    const float* thr = (const float*)d_in[6];
    float* out = (float*)d_out;

    proj_kernel<<<dim3(HID/64, (NB*SEQ)/64, 3), 256>>>(x, Wq, Wk, Wv);
    scores_kernel<<<dim3(SEQ/64, SEQ/64, NBH), 256>>>();
    topk_softmax_kernel<<<NBH * SEQ, 256>>>(thr);
    av_kernel<<<dim3(1, SEQ/64, NBH), 256>>>();
    final_kernel<<<dim3(HID/64, (NB*SEQ)/64, 1), 256>>>(Wo, bo, out);
}

// round 3
// speedup vs baseline: 1.2052x; 1.2052x over previous
#include <cuda_runtime.h>
#include <math.h>

#define HID    1024
#define NHEADS 16
#define HDIM   64
#define NB     2
#define SEQ    2048
#define NBH    (NB*NHEADS)
#define KKEEP  1024

// ---------------- scratch (allocation-free: __device__ globals) ----------------
__device__ float g_q[(size_t)NBH * SEQ * HDIM];     // [B,H,S,D]  16 MB
__device__ float g_k[(size_t)NBH * SEQ * HDIM];     // 16 MB
__device__ float g_v[(size_t)NBH * SEQ * HDIM];     // 16 MB
__device__ float g_p[(size_t)NBH * SEQ * SEQ];      // [B,H,S,S]  536 MB (scores -> probs in-place)
__device__ float g_ctx[(size_t)NB * SEQ * HID];     // [B,S,H*D]  16 MB

// ---------------- reduces ----------------
__device__ __forceinline__ float warp_max_f(float v) {
#pragma unroll
    for (int o = 16; o > 0; o >>= 1) v = fmaxf(v, __shfl_xor_sync(0xffffffffu, v, o));
    return v;
}
__device__ __forceinline__ float warp_sum_f(float v) {
#pragma unroll
    for (int o = 16; o > 0; o >>= 1) v += __shfl_xor_sync(0xffffffffu, v, o);
    return v;
}
__device__ __forceinline__ float block_max_f(float v, float* sm) {
    v = warp_max_f(v);
    if ((threadIdx.x & 31) == 0) sm[threadIdx.x >> 5] = v;
    __syncthreads();
    if (threadIdx.x == 0) {
        float r = sm[0];
#pragma unroll
        for (int i = 1; i < 8; i++) r = fmaxf(r, sm[i]);
        sm[0] = r;
    }
    __syncthreads();
    v = sm[0];
    __syncthreads();
    return v;
}
__device__ __forceinline__ float block_sum_f(float v, float* sm) {
    v = warp_sum_f(v);
    if ((threadIdx.x & 31) == 0) sm[threadIdx.x >> 5] = v;
    __syncthreads();
    if (threadIdx.x == 0) {
        float r = sm[0];
#pragma unroll
        for (int i = 1; i < 8; i++) r += sm[i];
        sm[0] = r;
    }
    __syncthreads();
    v = sm[0];
    __syncthreads();
    return v;
}

// =====================================================================
// 128x128 NT SGEMM core (A[M,K] row-major, B[N,K] row-major), BK=8,
// 256 threads, 8x8 per thread, double-buffered smem.
// =====================================================================
#define SM_STRIDE 136   // 128 + 8 pad, multiple of 4 (float4-aligned rows)

#define NT_GEMM_BODY(APTR, BPTR, KDIM)                                          \
    __shared__ float As[2][8][SM_STRIDE];                                       \
    __shared__ float Bs[2][8][SM_STRIDE];                                       \
    int tid = threadIdx.x;                                                      \
    int m0 = blockIdx.y * 128;                                                  \
    int n0 = blockIdx.x * 128;                                                  \
    int lr = tid >> 1;                 /* 0..127 */                             \
    int lc = (tid & 1) << 2;           /* 0 or 4 */                             \
    int tx = tid & 15, ty = tid >> 4;                                           \
    float acc[8][8] = {};                                                       \
    const int nk = (KDIM) / 8;                                                  \
    {                                                                           \
        float4 a4 = *(const float4*)((APTR) + (size_t)(m0 + lr) * (KDIM) + lc); \
        float4 b4 = *(const float4*)((BPTR) + (size_t)(n0 + lr) * (KDIM) + lc); \
        As[0][lc+0][lr] = a4.x; As[0][lc+1][lr] = a4.y;                         \
        As[0][lc+2][lr] = a4.z; As[0][lc+3][lr] = a4.w;                         \
        Bs[0][lc+0][lr] = b4.x; Bs[0][lc+1][lr] = b4.y;                         \
        Bs[0][lc+2][lr] = b4.z; Bs[0][lc+3][lr] = b4.w;                         \
    }                                                                           \
    __syncthreads();                                                            \
    for (int kt = 0; kt < nk; kt++) {                                           \
        int cur = kt & 1;                                                       \
        float4 an, bn;                                                          \
        if (kt + 1 < nk) {                                                      \
            an = *(const float4*)((APTR) + (size_t)(m0 + lr) * (KDIM) + (kt+1)*8 + lc); \
            bn = *(const float4*)((BPTR) + (size_t)(n0 + lr) * (KDIM) + (kt+1)*8 + lc); \
        }                                                                       \
        _Pragma("unroll")                                                       \
        for (int kk = 0; kk < 8; kk++) {                                        \
            float4 a0 = *(const float4*)&As[cur][kk][ty << 3];                  \
            float4 a1 = *(const float4*)&As[cur][kk][(ty << 3) + 4];            \
            float4 b0 = *(const float4*)&Bs[cur][kk][tx << 3];                  \
            float4 b1 = *(const float4*)&Bs[cur][kk][(tx << 3) + 4];            \
            float ar[8] = {a0.x,a0.y,a0.z,a0.w,a1.x,a1.y,a1.z,a1.w};            \
            float br[8] = {b0.x,b0.y,b0.z,b0.w,b1.x,b1.y,b1.z,b1.w};            \
            _Pragma("unroll")                                                   \
            for (int i = 0; i < 8; i++)                                         \
                _Pragma("unroll")                                               \
                for (int j = 0; j < 8; j++)                                     \
                    acc[i][j] += ar[i] * br[j];                                 \
        }                                                                       \
        if (kt + 1 < nk) {                                                      \
            int nxt = cur ^ 1;                                                  \
            As[nxt][lc+0][lr] = an.x; As[nxt][lc+1][lr] = an.y;                 \
            As[nxt][lc+2][lr] = an.z; As[nxt][lc+3][lr] = an.w;                 \
            Bs[nxt][lc+0][lr] = bn.x; Bs[nxt][lc+1][lr] = bn.y;                 \
            Bs[nxt][lc+2][lr] = bn.z; Bs[nxt][lc+3][lr] = bn.w;                 \
            __syncthreads();                                                    \
        }                                                                       \
    }

// ---------------- GEMM 1: QKV projection, scatter to [B,H,S,D] ----------------
__global__ void __launch_bounds__(256, 2) proj_kernel(const float* __restrict__ x,
                            const float* __restrict__ Wq,
                            const float* __restrict__ Wk,
                            const float* __restrict__ Wv) {
    const float* W;
    float* outp;
    if (blockIdx.z == 0)      { W = Wq; outp = g_q; }
    else if (blockIdx.z == 1) { W = Wk; outp = g_k; }
    else                      { W = Wv; outp = g_v; }

    NT_GEMM_BODY(x, W, HID)

    int n = n0 + (tx << 3);
    int h = n >> 6, d = n & 63;        // 8 consecutive cols stay in one head
#pragma unroll
    for (int i = 0; i < 8; i++) {
        int m = m0 + (ty << 3) + i;
        int b = m >> 11, s = m & (SEQ - 1);
        float* o = outp + (((size_t)(b * NHEADS + h) * SEQ + s) * HDIM + d);
        *(float4*)(o)     = make_float4(acc[i][0], acc[i][1], acc[i][2], acc[i][3]);
        *(float4*)(o + 4) = make_float4(acc[i][4], acc[i][5], acc[i][6], acc[i][7]);
    }
}

// ---------------- GEMM 2: scores = Q K^T * 1/8 per (b,h) ----------------
__global__ void __launch_bounds__(256, 2) scores_kernel() {
    int bh = blockIdx.z;
    const float* A  = g_q + (size_t)bh * SEQ * HDIM;
    const float* Bm = g_k + (size_t)bh * SEQ * HDIM;
    float* C = g_p + (size_t)bh * SEQ * SEQ;

    NT_GEMM_BODY(A, Bm, HDIM)

#pragma unroll
    for (int i = 0; i < 8; i++) {
        int m = m0 + (ty << 3) + i;
        float* o = C + (size_t)m * SEQ + n0 + (tx << 3);
        *(float4*)(o)     = make_float4(acc[i][0]*0.125f, acc[i][1]*0.125f,
                                        acc[i][2]*0.125f, acc[i][3]*0.125f);
        *(float4*)(o + 4) = make_float4(acc[i][4]*0.125f, acc[i][5]*0.125f,
                                        acc[i][6]*0.125f, acc[i][7]*0.125f);
    }
}

// ---------------- GEMM 4: out = ctx @ Wo^T + bo ----------------
__global__ void __launch_bounds__(256, 2) final_kernel(const float* __restrict__ Wo,
                             const float* __restrict__ bo,
                             float* __restrict__ out) {
    const float* ctx = g_ctx;

    NT_GEMM_BODY(ctx, Wo, HID)

    int n = n0 + (tx << 3);
    float4 bias0 = *(const float4*)(bo + n);
    float4 bias1 = *(const float4*)(bo + n + 4);
#pragma unroll
    for (int i = 0; i < 8; i++) {
        int m = m0 + (ty << 3) + i;
        float* o = out + (size_t)m * HID + n;
        *(float4*)(o)     = make_float4(acc[i][0]+bias0.x, acc[i][1]+bias0.y,
                                        acc[i][2]+bias0.z, acc[i][3]+bias0.w);
        *(float4*)(o + 4) = make_float4(acc[i][4]+bias1.x, acc[i][5]+bias1.y,
                                        acc[i][6]+bias1.z, acc[i][7]+bias1.w);
    }
}

// ---------------- kernel 3: exact top-k(1024) + threshold + masked softmax ----------------
// One block (256 thr) per score row. Exact k-th largest via 3-level histogram
// radix select (11 + 11 + 10 bits) over order-preserving uint keys.
__global__ void __launch_bounds__(256) topk_softmax_kernel(const float* __restrict__ thr_ptr) {
    __shared__ unsigned hist[2048];
    __shared__ unsigned chunk[257];
    __shared__ float smf[8];
    __shared__ unsigned s_bin, s_kr;

    size_t row = blockIdx.x;
    float* p = g_p + row * SEQ;
    int tid = threadIdx.x;

    float v[8];
    unsigned key[8];
    bool act[8];
#pragma unroll
    for (int i = 0; i < 8; i++) {
        v[i] = p[tid + (i << 8)];
        unsigned bb = __float_as_uint(v[i]);
        key[i] = (bb & 0x80000000u) ? ~bb : (bb | 0x80000000u);
        act[i] = true;
    }

    float lm = v[0];
#pragma unroll
    for (int i = 1; i < 8; i++) lm = fmaxf(lm, v[i]);
    float m = block_max_f(lm, smf);

    unsigned Kr = KKEEP;
    unsigned prefixKey = 0;

#pragma unroll
    for (int lvl = 0; lvl < 3; lvl++) {
        const int shift = (lvl == 0) ? 21 : (lvl == 1) ? 10 : 0;
        const unsigned mask = (lvl == 2) ? 1023u : 2047u;

        for (int i = tid; i < 2048; i += 256) hist[i] = 0u;
        __syncthreads();
#pragma unroll
        for (int i = 0; i < 8; i++)
            if (act[i]) atomicAdd(&hist[(key[i] >> shift) & mask], 1u);
        __syncthreads();

        unsigned cs = 0;
#pragma unroll
        for (int j = 0; j < 8; j++) cs += hist[(tid << 3) + j];
        chunk[tid] = cs;
        if (tid == 0) chunk[256] = 0u;
        __syncthreads();

        // inclusive suffix scan: chunk[t] = sum_{u>=t} counts
        for (int off = 1; off < 256; off <<= 1) {
            unsigned add = (tid + off < 256) ? chunk[tid + off] : 0u;
            __syncthreads();
            chunk[tid] += add;
            __syncthreads();
        }

        unsigned sfx  = chunk[tid];
        unsigned sfxn = chunk[tid + 1];   // chunk[256]=0 sentinel
        if (sfx >= Kr && sfxn < Kr) {
            unsigned cum = sfxn;
#pragma unroll
            for (int j = 7; j >= 0; j--) {
                unsigned h = hist[(tid << 3) + j];
                cum += h;
                if (cum >= Kr) {
                    s_bin = (tid << 3) + j;
                    s_kr  = Kr - (cum - h);
                    break;
                }
            }
        }
        __syncthreads();
        unsigned b = s_bin;
        Kr = s_kr;
        prefixKey |= b << shift;
        if (lvl < 2) {
#pragma unroll
            for (int i = 0; i < 8; i++)
                act[i] = act[i] && (((key[i] >> shift) & mask) == b);
        }
        __syncthreads();
    }

    float kth = __uint_as_float((prefixKey & 0x80000000u) ? (prefixKey ^ 0x80000000u)
                                                          : ~prefixKey);

    float thr = thr_ptr[0];
    thr = fminf(fmaxf(thr, 0.0f), 1.0f);
    float teff = fmaxf(kth, thr);   // keep iff v >= kth AND v >= thr

    float e[8];
    float ls = 0.0f;
#pragma unroll
    for (int i = 0; i < 8; i++) {
        e[i] = (v[i] >= teff) ? expf(v[i] - m) : 0.0f;
        ls += e[i];
    }
    float s = block_sum_f(ls, smf);
    float inv = 1.0f / s;
#pragma unroll
    for (int i = 0; i < 8; i++) p[tid + (i << 8)] = e[i] * inv;
}

// ---------------- GEMM 3: ctx = P @ V per (b,h) (NN), 128x64 tile, 8x8/thr ----------------
__global__ void __launch_bounds__(128) av_kernel() {
    int bh = blockIdx.z;
    int b = bh >> 4, h = bh & 15;
    const float* A  = g_p + (size_t)bh * SEQ * SEQ;    // [S,S] row-major
    const float* Bv = g_v + (size_t)bh * SEQ * HDIM;   // [S,64] row-major (NN)

    __shared__ float As[2][8][SM_STRIDE];
    __shared__ float Bs[2][8][72];

    int tid = threadIdx.x;
    int m0 = blockIdx.y * 128;
    int tx = tid & 7, ty = tid >> 3;       // 8x16 thread grid, 8x8 each
    int br_ = tid >> 4, bc_ = (tid & 15) << 2;   // B loader: 8 rows x 64 cols

    float acc[8][8] = {};
    const int nk = SEQ / 8;

    {
        float4 a0 = *(const float4*)(A + (size_t)(m0 + tid) * SEQ + 0);
        float4 a1 = *(const float4*)(A + (size_t)(m0 + tid) * SEQ + 4);
        As[0][0][tid] = a0.x; As[0][1][tid] = a0.y; As[0][2][tid] = a0.z; As[0][3][tid] = a0.w;
        As[0][4][tid] = a1.x; As[0][5][tid] = a1.y; As[0][6][tid] = a1.z; As[0][7][tid] = a1.w;
        float4 b4 = *(const float4*)(Bv + (size_t)br_ * HDIM + bc_);
        *(float4*)&Bs[0][br_][bc_] = b4;
    }
    __syncthreads();

    for (int kt = 0; kt < nk; kt++) {
        int cur = kt & 1;
        float4 an0, an1, bn;
        if (kt + 1 < nk) {
            an0 = *(const float4*)(A + (size_t)(m0 + tid) * SEQ + (kt+1)*8);
            an1 = *(const float4*)(A + (size_t)(m0 + tid) * SEQ + (kt+1)*8 + 4);
            bn  = *(const float4*)(Bv + (size_t)((kt+1)*8 + br_) * HDIM + bc_);
        }
#pragma unroll
        for (int kk = 0; kk < 8; kk++) {
            float4 a0 = *(const float4*)&As[cur][kk][ty << 3];
            float4 a1 = *(const float4*)&As[cur][kk][(ty << 3) + 4];
            float4 b0 = *(const float4*)&Bs[cur][kk][tx << 3];
            float4 b1 = *(const float4*)&Bs[cur][kk][(tx << 3) + 4];
            float ar[8] = {a0.x,a0.y,a0.z,a0.w,a1.x,a1.y,a1.z,a1.w};
            float br[8] = {b0.x,b0.y,b0.z,b0.w,b1.x,b1.y,b1.z,b1.w};
#pragma unroll
            for (int i = 0; i < 8; i++)
#pragma unroll
                for (int j = 0; j < 8; j++)
                    acc[i][j] += ar[i] * br[j];
        }
        if (kt + 1 < nk) {
            int nxt = cur ^ 1;
            As[nxt][0][tid] = an0.x; As[nxt][1][tid] = an0.y;
            As[nxt][2][tid] = an0.z; As[nxt][3][tid] = an0.w;
            As[nxt][4][tid] = an1.x; As[nxt][5][tid] = an1.y;
            As[nxt][6][tid] = an1.z; As[nxt][7][tid] = an1.w;
            *(float4*)&Bs[nxt][br_][bc_] = bn;
            __syncthreads();
        }
    }

    int nc = (tx << 3);   // col within head (0..56)
#pragma unroll
    for (int i = 0; i < 8; i++) {
        int m = m0 + (ty << 3) + i;   // query position s
        float* o = g_ctx + ((size_t)(b * SEQ + m) * HID + h * HDIM + nc);
        *(float4*)(o)     = make_float4(acc[i][0], acc[i][1], acc[i][2], acc[i][3]);
        *(float4*)(o + 4) = make_float4(acc[i][4], acc[i][5], acc[i][6], acc[i][7]);
    }
}

// ---------------- launch ----------------
extern "C" void kernel_launch(void* const* d_in, const int* in_sizes, int n_in,
                              void* d_out, int out_size) {
    const float* x   = (const float*)d_in[0];
    const float* Wq  = (const float*)d_in[1];
    const float* Wk  = (const float*)d_in[2];
    const float* Wv  = (const float*)d_in[3];
    const float* Wo  = (const float*)d_in[4];
    const float* bo  = (const float*)d_in[5];
    const float* thr = (const float*)d_in[6];
    float* out = (float*)d_out;

    proj_kernel<<<dim3(HID/128, (NB*SEQ)/128, 3), 256>>>(x, Wq, Wk, Wv);
    scores_kernel<<<dim3(SEQ/128, SEQ/128, NBH), 256>>>();
    topk_softmax_kernel<<<NBH * SEQ, 256>>>(thr);
    av_kernel<<<dim3(1, SEQ/128, NBH), 128>>>();
    final_kernel<<<dim3(HID/128, (NB*SEQ)/128, 1), 256>>>(Wo, bo, out);
}